// round 3
// baseline (speedup 1.0000x reference)
#include <cuda_runtime.h>

#define C      21
#define NSEG   500
#define EPSF   1e-5f
#define TBL    (NSEG * C)

// Scratch (no allocations allowed): segment log-sum table, combined coefficient
// table, and per-segment "row is all zero" skip flag.
__device__ float g_segA[TBL];
__device__ float g_Ct[TBL];
__device__ int   g_flag[NSEG];

// ---------------------------------------------------------------------------
// K0: zero the global accumulator (must re-run every graph replay).
// ---------------------------------------------------------------------------
__global__ void k_zero() {
    int i = blockIdx.x * blockDim.x + threadIdx.x;
    if (i < TBL) g_segA[i] = 0.f;
}

// ---------------------------------------------------------------------------
// K1: per-pixel softmax -> log(q+eps) -> segment accumulate.
// Shared-memory privatized accumulator per block, block atomics, then one
// global-atomic flush per block (296 blocks x 10.5K entries).
// ---------------------------------------------------------------------------
__global__ __launch_bounds__(256, 2)
void k_accum(const float* __restrict__ ql, const int* __restrict__ sp, int HW) {
    __shared__ float acc[TBL];
    for (int i = threadIdx.x; i < TBL; i += blockDim.x) acc[i] = 0.f;
    __syncthreads();

    int stride = gridDim.x * blockDim.x;
    for (int p = blockIdx.x * blockDim.x + threadIdx.x; p < HW; p += stride) {
        float x[C];
        float m = -3.402823466e38f;
#pragma unroll
        for (int c = 0; c < C; c++) {
            x[c] = ql[c * HW + p];          // coalesced per-class across warp
            m = fmaxf(m, x[c]);
        }
        float S = 0.f;
#pragma unroll
        for (int c = 0; c < C; c++) {
            x[c] = __expf(x[c] - m);
            S += x[c];
        }
        float invS = 1.f / S;
        float* row = acc + sp[p] * C;
#pragma unroll
        for (int c = 0; c < C; c++) {
            float lq = __logf(fmaf(x[c], invS, EPSF));   // log(softmax + eps)
            atomicAdd(row + c, lq);                       // ATOMS (spread addrs)
        }
    }
    __syncthreads();
    for (int i = threadIdx.x; i < TBL; i += blockDim.x)
        atomicAdd(&g_segA[i], acc[i]);
}

// ---------------------------------------------------------------------------
// K1b: tiny table kernel.
//   Ct[s,c] = (lw0[c]-hw0)*exp(A) + (lw1[c]-hw1)*exp(499*A)
//   flag[s] = (row has any nonzero Ct)
// exp(A) underflows to 0 exactly when exp(A - denom) does in the reference
// (A ~ -7500 here, denom in [-12, ~0]), so Ct==0 <=> f_sp == f_att == 0.
// ---------------------------------------------------------------------------
__global__ void k_table(const float* __restrict__ lw, const float* __restrict__ hw) {
    int s = blockIdx.x * blockDim.x + threadIdx.x;
    if (s >= NSEG) return;
    float h0 = hw[0], h1 = hw[1];
    int f = 0;
#pragma unroll
    for (int c = 0; c < C; c++) {
        float A  = g_segA[s * C + c];
        float ct = (lw[c] - h0) * expf(A) + (lw[C + c] - h1) * expf(499.f * A);
        g_Ct[s * C + c] = ct;
        f |= (ct != 0.f);
    }
    g_flag[s] = f;
}

// ---------------------------------------------------------------------------
// K2: output. Common (underflow) path is a pure streaming write of
// base = hw0 + hw1 (bit-identical to reference's hw0*(1-0)+hw1*(1-0)).
// Rare path uses f = exp(A)/(q_mod+eps) == exp(A - denom).
// ---------------------------------------------------------------------------
__global__ __launch_bounds__(256)
void k_out(const float* __restrict__ ql, const int* __restrict__ sp,
           const float* __restrict__ hw, float* __restrict__ out, int HW) {
    int p = blockIdx.x * blockDim.x + threadIdx.x;
    if (p >= HW) return;
    int s = sp[p];
    float base = hw[0] + hw[1];
    if (!g_flag[s]) {
#pragma unroll
        for (int c = 0; c < C; c++) out[c * HW + p] = base;
    } else {
        float x[C];
        float m = -3.402823466e38f;
#pragma unroll
        for (int c = 0; c < C; c++) {
            x[c] = ql[c * HW + p];
            m = fmaxf(m, x[c]);
        }
        float S = 0.f;
#pragma unroll
        for (int c = 0; c < C; c++) {
            x[c] = expf(x[c] - m);
            S += x[c];
        }
        float invS = 1.f / S;
#pragma unroll
        for (int c = 0; c < C; c++) {
            float q  = x[c] * invS;
            float qm = (q == 0.f) ? 1.f : q;      // q + (q==0)
            float invq = 1.f / (qm + EPSF);       // = exp(-denom)
            out[c * HW + p] = base + g_Ct[s * C + c] * invq;
        }
    }
}

// ---------------------------------------------------------------------------
// Inputs (metadata order): q_logits f32 (21,1024,1024), low_weights f32 (2,21),
// high_weights f32 (2,), sp_map int32 (1024,1024). Output f32 (21,1024,1024).
// ---------------------------------------------------------------------------
extern "C" void kernel_launch(void* const* d_in, const int* in_sizes, int n_in,
                              void* d_out, int out_size) {
    const float* ql = (const float*)d_in[0];
    const float* lw = (const float*)d_in[1];
    const float* hw = (const float*)d_in[2];
    const int*   sp = (const int*)d_in[3];
    float* out = (float*)d_out;
    int HW = in_sizes[0] / C;

    k_zero<<<(TBL + 255) / 256, 256>>>();
    k_accum<<<296, 256>>>(ql, sp, HW);
    k_table<<<(NSEG + 255) / 256, 256>>>(lw, hw);
    k_out<<<(HW + 255) / 256, 256>>>(ql, sp, hw, out, HW);
}

// round 4
// speedup vs baseline: 1.7323x; 1.7323x over previous
#include <cuda_runtime.h>

#define C      21
#define NSEG   500
#define EPSF   1e-5f
#define TBL    (NSEG * C)
// Need full per-class treatment only if T'[s] < THRESH.
// exp(A - denom) can be nonzero only if A > -115 (denorm exp cutoff -103.3,
// denom >= log(eps) = -11.5). A <= -T'[s], margin 15 for fp accumulation error.
#define THRESH 130.0f

// Scratch (__device__ globals; no allocations allowed).
__device__ float g_T[NSEG];     // per-segment certificate sum
__device__ float g_segA[TBL];   // exact per-(seg,class) log-sums (fallback path)
__device__ float g_Ct[TBL];     // combined coefficient table
__device__ int   g_need[NSEG];  // segment needs exact pass
__device__ int   g_flag[NSEG];  // segment row has any nonzero Ct

// ---------------------------------------------------------------------------
// K0: zero scratch (re-runs every graph replay).
// ---------------------------------------------------------------------------
__global__ void k_zero() {
    int i = blockIdx.x * blockDim.x + threadIdx.x;
    if (i < NSEG) g_T[i] = 0.f;
    if (i < TBL)  g_segA[i] = 0.f;
}

// ---------------------------------------------------------------------------
// K1: per-pixel softmax denominator -> ONE shared atomic per pixel.
//   T'[s] += logS_p - 2.2e-4   (valid upper-bound certificate: A[s,c] <= -T'[s])
// float4: each thread handles 4 consecutive pixels; 21 LDG.128 per group.
// ---------------------------------------------------------------------------
__global__ __launch_bounds__(256, 2)
void k_bound(const float* __restrict__ ql, const int* __restrict__ sp, int HW) {
    __shared__ float accT[NSEG];
    for (int i = threadIdx.x; i < NSEG; i += 256) accT[i] = 0.f;
    __syncthreads();

    int ng = HW >> 2;
    int stride = gridDim.x * blockDim.x;
    for (int g = blockIdx.x * blockDim.x + threadIdx.x; g < ng; g += stride) {
        float4 x[C];
        float4 m = make_float4(-3.402823466e38f, -3.402823466e38f,
                               -3.402823466e38f, -3.402823466e38f);
#pragma unroll
        for (int c = 0; c < C; c++) {
            x[c] = *((const float4*)(ql + (size_t)c * HW) + g);
            m.x = fmaxf(m.x, x[c].x); m.y = fmaxf(m.y, x[c].y);
            m.z = fmaxf(m.z, x[c].z); m.w = fmaxf(m.w, x[c].w);
        }
        float4 S = make_float4(0.f, 0.f, 0.f, 0.f);
#pragma unroll
        for (int c = 0; c < C; c++) {
            S.x += __expf(x[c].x - m.x); S.y += __expf(x[c].y - m.y);
            S.z += __expf(x[c].z - m.z); S.w += __expf(x[c].w - m.w);
        }
        int4 s4 = ((const int4*)sp)[g];
        atomicAdd(&accT[s4.x], __logf(S.x) - 2.2e-4f);
        atomicAdd(&accT[s4.y], __logf(S.y) - 2.2e-4f);
        atomicAdd(&accT[s4.z], __logf(S.z) - 2.2e-4f);
        atomicAdd(&accT[s4.w], __logf(S.w) - 2.2e-4f);
    }
    __syncthreads();
    for (int i = threadIdx.x; i < NSEG; i += 256)
        if (accT[i] != 0.f) atomicAdd(&g_T[i], accT[i]);
}

// ---------------------------------------------------------------------------
// K2: classify segments.
// ---------------------------------------------------------------------------
__global__ void k_need() {
    int s = blockIdx.x * blockDim.x + threadIdx.x;
    if (s < NSEG) g_need[s] = (g_T[s] < THRESH) ? 1 : 0;
}

// ---------------------------------------------------------------------------
// K3: exact fallback accumulation — only touches q for pixels whose segment
// survived the certificate (expected: none). Common path reads only sp+flags.
// ---------------------------------------------------------------------------
__global__ __launch_bounds__(256)
void k_fallback(const float* __restrict__ ql, const int* __restrict__ sp, int HW) {
    int ng = HW >> 2;
    int stride = gridDim.x * blockDim.x;
    for (int g = blockIdx.x * blockDim.x + threadIdx.x; g < ng; g += stride) {
        int4 s4 = ((const int4*)sp)[g];
        int n0 = g_need[s4.x], n1 = g_need[s4.y], n2 = g_need[s4.z], n3 = g_need[s4.w];
        if (!(n0 | n1 | n2 | n3)) continue;
        int segs[4] = {s4.x, s4.y, s4.z, s4.w};
        int nd[4]   = {n0, n1, n2, n3};
        for (int k = 0; k < 4; k++) {
            if (!nd[k]) continue;
            int p = g * 4 + k;
            float x[C];
            float m = -3.402823466e38f;
#pragma unroll
            for (int c = 0; c < C; c++) {
                x[c] = ql[(size_t)c * HW + p];
                m = fmaxf(m, x[c]);
            }
            float S = 0.f;
#pragma unroll
            for (int c = 0; c < C; c++) { x[c] = expf(x[c] - m); S += x[c]; }
            float invS = 1.f / S;
            float* row = g_segA + segs[k] * C;
#pragma unroll
            for (int c = 0; c < C; c++)
                atomicAdd(row + c, logf(fmaf(x[c], invS, EPSF)));
        }
    }
}

// ---------------------------------------------------------------------------
// K4: coefficient table. Non-needed segments: flag=0 (row provably all-zero).
// ---------------------------------------------------------------------------
__global__ void k_table(const float* __restrict__ lw, const float* __restrict__ hw) {
    int s = blockIdx.x * blockDim.x + threadIdx.x;
    if (s >= NSEG) return;
    if (!g_need[s]) { g_flag[s] = 0; return; }
    float h0 = hw[0], h1 = hw[1];
    int f = 0;
#pragma unroll
    for (int c = 0; c < C; c++) {
        float A  = g_segA[s * C + c];
        float ct = (lw[c] - h0) * expf(A) + (lw[C + c] - h1) * expf(499.f * A);
        g_Ct[s * C + c] = ct;
        f |= (ct != 0.f);
    }
    g_flag[s] = f;
}

// ---------------------------------------------------------------------------
// K5: output. Common path: pure STG.128 stream of base = hw0 + hw1
// (bit-identical to reference when f_sp = f_att = 0). Rare path: exact.
// ---------------------------------------------------------------------------
__global__ __launch_bounds__(256)
void k_out(const float* __restrict__ ql, const int* __restrict__ sp,
           const float* __restrict__ hw, float* __restrict__ out, int HW) {
    int g = blockIdx.x * blockDim.x + threadIdx.x;
    int ng = HW >> 2;
    if (g >= ng) return;
    int4 s4 = ((const int4*)sp)[g];
    float base = hw[0] + hw[1];
    int f0 = g_flag[s4.x], f1 = g_flag[s4.y], f2 = g_flag[s4.z], f3 = g_flag[s4.w];
    if (!(f0 | f1 | f2 | f3)) {
        float4 b4 = make_float4(base, base, base, base);
#pragma unroll
        for (int c = 0; c < C; c++)
            *((float4*)(out + (size_t)c * HW) + g) = b4;
    } else {
        for (int k = 0; k < 4; k++) {
            int p = g * 4 + k;
            int s = sp[p];
            if (!g_flag[s]) {
#pragma unroll
                for (int c = 0; c < C; c++) out[(size_t)c * HW + p] = base;
                continue;
            }
            float x[C];
            float m = -3.402823466e38f;
#pragma unroll
            for (int c = 0; c < C; c++) {
                x[c] = ql[(size_t)c * HW + p];
                m = fmaxf(m, x[c]);
            }
            float S = 0.f;
#pragma unroll
            for (int c = 0; c < C; c++) { x[c] = expf(x[c] - m); S += x[c]; }
            float invS = 1.f / S;
#pragma unroll
            for (int c = 0; c < C; c++) {
                float q  = x[c] * invS;
                float qm = (q == 0.f) ? 1.f : q;
                out[(size_t)c * HW + p] = base + g_Ct[s * C + c] / (qm + EPSF);
            }
        }
    }
}

// ---------------------------------------------------------------------------
// Inputs: q_logits f32 (21,1024,1024), low_weights f32 (2,21),
// high_weights f32 (2,), sp_map int32 (1024,1024). Output f32 (21,1024,1024).
// ---------------------------------------------------------------------------
extern "C" void kernel_launch(void* const* d_in, const int* in_sizes, int n_in,
                              void* d_out, int out_size) {
    const float* ql = (const float*)d_in[0];
    const float* lw = (const float*)d_in[1];
    const float* hw = (const float*)d_in[2];
    const int*   sp = (const int*)d_in[3];
    float* out = (float*)d_out;
    int HW = in_sizes[0] / C;
    int ng = HW >> 2;

    k_zero<<<(TBL + 255) / 256, 256>>>();
    k_bound<<<296, 256>>>(ql, sp, HW);
    k_need<<<(NSEG + 255) / 256, 256>>>();
    k_fallback<<<296, 256>>>(ql, sp, HW);
    k_table<<<(NSEG + 255) / 256, 256>>>(lw, hw);
    k_out<<<(ng + 255) / 256, 256>>>(ql, sp, hw, out, HW);
}

// round 6
// speedup vs baseline: 2.0774x; 1.1992x over previous
#include <cuda_runtime.h>

#define C      21
#define NSEG   500
#define EPSF   1e-5f
#define TBL    (NSEG * C)
#define GRID   296
#define BLK    256
// Segment needs exact treatment only if T'[s] < THRESH.
// exp(A - denom) nonzero requires A > -115 (denorm exp cutoff -103.3,
// denom >= log(eps) = -11.5). A <= -T'[s]; 15 units of fp-accum margin.
#define THRESH 130.0f

// Per-segment certificate sum. Zero at module load; k_need re-zeros it after
// consuming it, so every kernel_launch invocation starts AND ends with 0.
__device__ float g_T[NSEG];
__device__ int   g_need[NSEG];

// ---------------------------------------------------------------------------
// K_main: one streaming pass over q_logits.
//   - per-pixel online max + exp-sum -> logS certificate (1 shared atomic/px)
//   - writes out[c][p] = hw0 + hw1 for every pixel (bit-identical to the
//     reference whenever f_sp = f_att = 0, which the certificate proves)
//   - block flushes its 500-float partial into g_T via global atomics
// ---------------------------------------------------------------------------
__global__ __launch_bounds__(BLK)
void k_main(const float* __restrict__ ql, const int* __restrict__ sp,
            const float* __restrict__ hw, float* __restrict__ out, int HW) {
    __shared__ float accT[NSEG];
    for (int i = threadIdx.x; i < NSEG; i += BLK) accT[i] = 0.f;
    __syncthreads();

    float base = __ldg(hw) + __ldg(hw + 1);
    int stride = GRID * BLK;
    for (int p = blockIdx.x * BLK + threadIdx.x; p < HW; p += stride) {
        float x[C];
        float m = -3.402823466e38f;
#pragma unroll
        for (int c = 0; c < C; c++) {
            x[c] = __ldcs(ql + (size_t)c * HW + p);   // coalesced, touch-once
            m = fmaxf(m, x[c]);
        }
        float S = 0.f;
#pragma unroll
        for (int c = 0; c < C; c++) S += __expf(x[c] - m);
        atomicAdd(&accT[sp[p]], __logf(S) - 2.2e-4f);
#pragma unroll
        for (int c = 0; c < C; c++)
            __stcs(out + (size_t)c * HW + p, base);    // streaming store
    }
    __syncthreads();
    for (int i = threadIdx.x; i < NSEG; i += BLK)
        if (accT[i] != 0.f) atomicAdd(&g_T[i], accT[i]);
}

// ---------------------------------------------------------------------------
// K_need: classify segments, then reset g_T for the next replay
// (same thread reads then clears -> no race, graph-replay safe).
// ---------------------------------------------------------------------------
__global__ void k_need() {
    int s = blockIdx.x * blockDim.x + threadIdx.x;
    if (s < NSEG) {
        g_need[s] = (g_T[s] < THRESH) ? 1 : 0;
        g_T[s] = 0.f;
    }
}

// ---------------------------------------------------------------------------
// K_rare: single-block gated exact path. Common case: load 500 flags,
// syncthreads_or, exit (~1us). Rare case (certificate failed for some
// segment): do the full exact computation in one block using smem tables,
// rewriting only pixels in flagged segments (the rest already hold `base`).
// ---------------------------------------------------------------------------
__global__ __launch_bounds__(1024)
void k_rare(const float* __restrict__ ql, const int* __restrict__ sp,
            const float* __restrict__ lw, const float* __restrict__ hw,
            float* __restrict__ out, int HW) {
    int t = threadIdx.x;
    int pred = (t < NSEG) ? g_need[t] : 0;
    if (!__syncthreads_or(pred)) return;

    __shared__ float segA[TBL];     // 42 KB: per-(seg,class) log-sums
    __shared__ float Ct[TBL];
    __shared__ int   flag[NSEG];
    for (int i = t; i < TBL; i += 1024) segA[i] = 0.f;
    __syncthreads();

    // exact accumulation for pixels in needed segments
    for (int p = t; p < HW; p += 1024) {
        int s = sp[p];
        if (!g_need[s]) continue;
        float x[C];
        float m = -3.402823466e38f;
#pragma unroll
        for (int c = 0; c < C; c++) { x[c] = ql[(size_t)c * HW + p]; m = fmaxf(m, x[c]); }
        float S = 0.f;
#pragma unroll
        for (int c = 0; c < C; c++) { x[c] = expf(x[c] - m); S += x[c]; }
        float invS = 1.f / S;
#pragma unroll
        for (int c = 0; c < C; c++)
            atomicAdd(&segA[s * C + c], logf(fmaf(x[c], invS, EPSF)));
    }
    __syncthreads();

    // coefficient table: Ct = (lw0-hw0)*exp(A) + (lw1-hw1)*exp(499A)
    if (t < NSEG) {
        float h0 = hw[0], h1 = hw[1];
        int f = 0;
        if (g_need[t]) {
#pragma unroll
            for (int c = 0; c < C; c++) {
                float A  = segA[t * C + c];
                float ct = (lw[c] - h0) * expf(A) + (lw[C + c] - h1) * expf(499.f * A);
                Ct[t * C + c] = ct;
                f |= (ct != 0.f);
            }
        }
        flag[t] = f;
    }
    __syncthreads();

    // rewrite pixels of flagged segments: out = base + Ct/(q_mod+eps)
    float base = hw[0] + hw[1];
    for (int p = t; p < HW; p += 1024) {
        int s = sp[p];
        if (!flag[s]) continue;
        float x[C];
        float m = -3.402823466e38f;
#pragma unroll
        for (int c = 0; c < C; c++) { x[c] = ql[(size_t)c * HW + p]; m = fmaxf(m, x[c]); }
        float S = 0.f;
#pragma unroll
        for (int c = 0; c < C; c++) { x[c] = expf(x[c] - m); S += x[c]; }
        float invS = 1.f / S;
#pragma unroll
        for (int c = 0; c < C; c++) {
            float q  = x[c] * invS;
            float qm = (q == 0.f) ? 1.f : q;
            out[(size_t)c * HW + p] = base + Ct[s * C + c] / (qm + EPSF);
        }
    }
}

// ---------------------------------------------------------------------------
// Inputs: q_logits f32 (21,1024,1024), low_weights f32 (2,21),
// high_weights f32 (2,), sp_map int32 (1024,1024). Output f32 (21,1024,1024).
// ---------------------------------------------------------------------------
extern "C" void kernel_launch(void* const* d_in, const int* in_sizes, int n_in,
                              void* d_out, int out_size) {
    const float* ql = (const float*)d_in[0];
    const float* lw = (const float*)d_in[1];
    const float* hw = (const float*)d_in[2];
    const int*   sp = (const int*)d_in[3];
    float* out = (float*)d_out;
    int HW = in_sizes[0] / C;

    k_main<<<GRID, BLK>>>(ql, sp, hw, out, HW);
    k_need<<<2, 256>>>();
    k_rare<<<1, 1024>>>(ql, sp, lw, hw, out, HW);
}

// round 7
// speedup vs baseline: 2.3611x; 1.1366x over previous
#include <cuda_runtime.h>

#define C      21
#define NSEG   500
#define EPSF   1e-5f
#define TBL    (NSEG * C)
#define GRID   296          // 2 blocks per SM (148 SMs)
#define BLK    1024         // 2 x 1024 = 2048 threads/SM = 100% occ
// Segment needs exact treatment only if T'[s] < THRESH.
// exp(A - denom) nonzero requires A > -115 (denorm exp cutoff -103.3,
// denom >= log(eps) = -11.5). A <= -T'[s]; 15 units of fp-accum margin.
#define THRESH 130.0f

// Per-segment certificate sum. Zero at module load; k_rare re-zeros it after
// consuming it, so every kernel_launch invocation starts AND ends with 0.
__device__ float g_T[NSEG];

// ---------------------------------------------------------------------------
// K_main: one streaming pass over q_logits.
//   - per-pixel online max + exp-sum -> logS certificate (1 shared atomic/px)
//   - writes out[c][p] = hw0 + hw1 for every pixel (bit-identical to the
//     reference whenever f_sp = f_att = 0, which the certificate proves)
//   - block flushes its 500-float partial into g_T via global atomics
// ---------------------------------------------------------------------------
__global__ __launch_bounds__(BLK, 2)
void k_main(const float* __restrict__ ql, const int* __restrict__ sp,
            const float* __restrict__ hw, float* __restrict__ out, int HW) {
    __shared__ float accT[NSEG];
    for (int i = threadIdx.x; i < NSEG; i += BLK) accT[i] = 0.f;
    __syncthreads();

    float base = __ldg(hw) + __ldg(hw + 1);
    int stride = GRID * BLK;
    for (int p = blockIdx.x * BLK + threadIdx.x; p < HW; p += stride) {
        float x[C];
        float m = -3.402823466e38f;
#pragma unroll
        for (int c = 0; c < C; c++) {
            x[c] = __ldcs(ql + (size_t)c * HW + p);   // coalesced, touch-once
            m = fmaxf(m, x[c]);
        }
        float S = 0.f;
#pragma unroll
        for (int c = 0; c < C; c++) S += __expf(x[c] - m);
        atomicAdd(&accT[sp[p]], __logf(S) - 2.2e-4f);
#pragma unroll
        for (int c = 0; c < C; c++)
            __stcs(out + (size_t)c * HW + p, base);    // streaming store
    }
    __syncthreads();
    for (int i = threadIdx.x; i < NSEG; i += BLK)
        if (accT[i] != 0.f) atomicAdd(&g_T[i], accT[i]);
}

// ---------------------------------------------------------------------------
// K_rare: single-block kernel. Head: classify segments from g_T (and reset
// g_T for the next graph replay -- same thread reads then clears, no race).
// Common case: no segment survives the certificate -> exit (~1us).
// Rare case: full exact computation in one block via smem tables, rewriting
// only pixels in flagged segments (all others already hold `base`).
// ---------------------------------------------------------------------------
__global__ __launch_bounds__(1024)
void k_rare(const float* __restrict__ ql, const int* __restrict__ sp,
            const float* __restrict__ lw, const float* __restrict__ hw,
            float* __restrict__ out, int HW) {
    __shared__ int s_need[NSEG];
    int t = threadIdx.x;
    int pred = 0;
    if (t < NSEG) {
        pred = (g_T[t] < THRESH) ? 1 : 0;
        s_need[t] = pred;
        g_T[t] = 0.f;                       // reset for next replay
    }
    if (!__syncthreads_or(pred)) return;

    __shared__ float segA[TBL];             // 42 KB: per-(seg,class) log-sums
    __shared__ float Ct[TBL];
    __shared__ int   flag[NSEG];
    for (int i = t; i < TBL; i += 1024) segA[i] = 0.f;
    __syncthreads();

    // exact accumulation for pixels in needed segments
    for (int p = t; p < HW; p += 1024) {
        int s = sp[p];
        if (!s_need[s]) continue;
        float x[C];
        float m = -3.402823466e38f;
#pragma unroll
        for (int c = 0; c < C; c++) { x[c] = ql[(size_t)c * HW + p]; m = fmaxf(m, x[c]); }
        float S = 0.f;
#pragma unroll
        for (int c = 0; c < C; c++) { x[c] = expf(x[c] - m); S += x[c]; }
        float invS = 1.f / S;
#pragma unroll
        for (int c = 0; c < C; c++)
            atomicAdd(&segA[s * C + c], logf(fmaf(x[c], invS, EPSF)));
    }
    __syncthreads();

    // coefficient table: Ct = (lw0-hw0)*exp(A) + (lw1-hw1)*exp(499A)
    if (t < NSEG) {
        float h0 = hw[0], h1 = hw[1];
        int f = 0;
        if (s_need[t]) {
#pragma unroll
            for (int c = 0; c < C; c++) {
                float A  = segA[t * C + c];
                float ct = (lw[c] - h0) * expf(A) + (lw[C + c] - h1) * expf(499.f * A);
                Ct[t * C + c] = ct;
                f |= (ct != 0.f);
            }
        }
        flag[t] = f;
    }
    __syncthreads();

    // rewrite pixels of flagged segments: out = base + Ct/(q_mod+eps)
    float base = hw[0] + hw[1];
    for (int p = t; p < HW; p += 1024) {
        int s = sp[p];
        if (!flag[s]) continue;
        float x[C];
        float m = -3.402823466e38f;
#pragma unroll
        for (int c = 0; c < C; c++) { x[c] = ql[(size_t)c * HW + p]; m = fmaxf(m, x[c]); }
        float S = 0.f;
#pragma unroll
        for (int c = 0; c < C; c++) { x[c] = expf(x[c] - m); S += x[c]; }
        float invS = 1.f / S;
#pragma unroll
        for (int c = 0; c < C; c++) {
            float q  = x[c] * invS;
            float qm = (q == 0.f) ? 1.f : q;
            out[(size_t)c * HW + p] = base + Ct[s * C + c] / (qm + EPSF);
        }
    }
}

// ---------------------------------------------------------------------------
// Inputs: q_logits f32 (21,1024,1024), low_weights f32 (2,21),
// high_weights f32 (2,), sp_map int32 (1024,1024). Output f32 (21,1024,1024).
// ---------------------------------------------------------------------------
extern "C" void kernel_launch(void* const* d_in, const int* in_sizes, int n_in,
                              void* d_out, int out_size) {
    const float* ql = (const float*)d_in[0];
    const float* lw = (const float*)d_in[1];
    const float* hw = (const float*)d_in[2];
    const int*   sp = (const int*)d_in[3];
    float* out = (float*)d_out;
    int HW = in_sizes[0] / C;

    k_main<<<GRID, BLK>>>(ql, sp, hw, out, HW);
    k_rare<<<1, 1024>>>(ql, sp, lw, hw, out, HW);
}

// round 8
// speedup vs baseline: 2.3985x; 1.0158x over previous
#include <cuda_runtime.h>

#define C      21
#define NSEG   500
#define EPSF   1e-5f
#define TBL    (NSEG * C)
#define GRID   296          // 2 blocks per SM (148 SMs)
#define BLK    1024         // 2 x 1024 = 2048 threads/SM = 100% occ
// Segment needs exact treatment only if T'[s] < THRESH.
// exp(A - denom) nonzero requires A > -115 (denorm exp cutoff -103.3,
// denom >= log(eps) = -11.5). A <= -T'[s]; 15 units of fp-accum margin.
#define THRESH 130.0f

// Per-segment certificate sum. Zero at module load; k_rare re-zeros it after
// consuming it, so every kernel_launch invocation starts AND ends with 0.
__device__ float g_T[NSEG];
// Rare-path scratch tables (device globals, NOT smem: keeps k_rare's shared
// footprint tiny so the common-path launch is cheap). Zeroed inside the rare
// branch immediately before use -> deterministic across graph replays.
__device__ float g_segA[TBL];
__device__ float g_Ct[TBL];

// ---------------------------------------------------------------------------
// K_main: one streaming pass over q_logits.
//   - per-pixel max + exp-sum -> logS certificate (1 shared atomic/px)
//   - writes out[c][p] = hw0 + hw1 for every pixel (bit-identical to the
//     reference whenever f_sp = f_att = 0, which the certificate proves)
//   - block flushes its 500-float partial into g_T via global atomics
// ---------------------------------------------------------------------------
__global__ __launch_bounds__(BLK, 2)
void k_main(const float* __restrict__ ql, const int* __restrict__ sp,
            const float* __restrict__ hw, float* __restrict__ out, int HW) {
    __shared__ float accT[NSEG];
    for (int i = threadIdx.x; i < NSEG; i += BLK) accT[i] = 0.f;
    __syncthreads();

    float base = __ldg(hw) + __ldg(hw + 1);
    int stride = GRID * BLK;
    for (int p = blockIdx.x * BLK + threadIdx.x; p < HW; p += stride) {
        float x[C];
        float m = -3.402823466e38f;
#pragma unroll
        for (int c = 0; c < C; c++) {
            x[c] = __ldcs(ql + (size_t)c * HW + p);   // coalesced, touch-once
            m = fmaxf(m, x[c]);
        }
        float S = 0.f;
#pragma unroll
        for (int c = 0; c < C; c++) S += __expf(x[c] - m);
        atomicAdd(&accT[sp[p]], __logf(S) - 2.2e-4f);
#pragma unroll
        for (int c = 0; c < C; c++)
            __stcs(out + (size_t)c * HW + p, base);    // streaming store
    }
    __syncthreads();
    for (int i = threadIdx.x; i < NSEG; i += BLK)
        if (accT[i] != 0.f) atomicAdd(&g_T[i], accT[i]);
}

// ---------------------------------------------------------------------------
// K_rare: single-block kernel, ~4 KB smem. Head: classify segments from g_T
// (and reset g_T for the next graph replay -- same thread reads then clears).
// Common case: no segment survives the certificate -> exit immediately.
// Rare case: full exact computation using global scratch tables, rewriting
// only pixels in flagged segments (all others already hold `base`).
// ---------------------------------------------------------------------------
__global__ __launch_bounds__(1024)
void k_rare(const float* __restrict__ ql, const int* __restrict__ sp,
            const float* __restrict__ lw, const float* __restrict__ hw,
            float* __restrict__ out, int HW) {
    __shared__ int s_need[NSEG];
    __shared__ int s_flag[NSEG];
    int t = threadIdx.x;
    int pred = 0;
    if (t < NSEG) {
        pred = (g_T[t] < THRESH) ? 1 : 0;
        s_need[t] = pred;
        g_T[t] = 0.f;                       // reset for next replay
    }
    if (!__syncthreads_or(pred)) return;

    // ---- rare path below (never taken on typical inputs) ----
    for (int i = t; i < TBL; i += 1024) g_segA[i] = 0.f;
    __syncthreads();
    __threadfence();

    // exact accumulation for pixels in needed segments
    for (int p = t; p < HW; p += 1024) {
        int s = sp[p];
        if (!s_need[s]) continue;
        float x[C];
        float m = -3.402823466e38f;
#pragma unroll
        for (int c = 0; c < C; c++) { x[c] = ql[(size_t)c * HW + p]; m = fmaxf(m, x[c]); }
        float S = 0.f;
#pragma unroll
        for (int c = 0; c < C; c++) { x[c] = expf(x[c] - m); S += x[c]; }
        float invS = 1.f / S;
#pragma unroll
        for (int c = 0; c < C; c++)
            atomicAdd(&g_segA[s * C + c], logf(fmaf(x[c], invS, EPSF)));
    }
    __syncthreads();
    __threadfence();

    // coefficient table: Ct = (lw0-hw0)*exp(A) + (lw1-hw1)*exp(499A)
    if (t < NSEG) {
        float h0 = hw[0], h1 = hw[1];
        int f = 0;
        if (s_need[t]) {
#pragma unroll
            for (int c = 0; c < C; c++) {
                float A  = g_segA[t * C + c];
                float ct = (lw[c] - h0) * expf(A) + (lw[C + c] - h1) * expf(499.f * A);
                g_Ct[t * C + c] = ct;
                f |= (ct != 0.f);
            }
        }
        s_flag[t] = f;
    }
    __syncthreads();
    __threadfence();

    // rewrite pixels of flagged segments: out = base + Ct/(q_mod+eps)
    float base = hw[0] + hw[1];
    for (int p = t; p < HW; p += 1024) {
        int s = sp[p];
        if (!s_flag[s]) continue;
        float x[C];
        float m = -3.402823466e38f;
#pragma unroll
        for (int c = 0; c < C; c++) { x[c] = ql[(size_t)c * HW + p]; m = fmaxf(m, x[c]); }
        float S = 0.f;
#pragma unroll
        for (int c = 0; c < C; c++) { x[c] = expf(x[c] - m); S += x[c]; }
        float invS = 1.f / S;
#pragma unroll
        for (int c = 0; c < C; c++) {
            float q  = x[c] * invS;
            float qm = (q == 0.f) ? 1.f : q;
            out[(size_t)c * HW + p] = base + g_Ct[s * C + c] / (qm + EPSF);
        }
    }
}

// ---------------------------------------------------------------------------
// Inputs: q_logits f32 (21,1024,1024), low_weights f32 (2,21),
// high_weights f32 (2,), sp_map int32 (1024,1024). Output f32 (21,1024,1024).
// ---------------------------------------------------------------------------
extern "C" void kernel_launch(void* const* d_in, const int* in_sizes, int n_in,
                              void* d_out, int out_size) {
    const float* ql = (const float*)d_in[0];
    const float* lw = (const float*)d_in[1];
    const float* hw = (const float*)d_in[2];
    const int*   sp = (const int*)d_in[3];
    float* out = (float*)d_out;
    int HW = in_sizes[0] / C;

    k_main<<<GRID, BLK>>>(ql, sp, hw, out, HW);
    k_rare<<<1, 1024>>>(ql, sp, lw, hw, out, HW);
}